// round 10
// baseline (speedup 1.0000x reference)
#include <cuda_runtime.h>

// Problem constants: B=2048, F=P*N=4096, C=10
#define F        4096
#define C        10

// wprep geometry: 80 blocks = (c, seg), each covers 512 f.
#define WSEG     8
#define WPREP_T  256
#define WF       (F / WSEG)
#define NWARP    (WPREP_T / 32)

// lse geometry: 512 threads, pt fully smem-resident, RG=4, f32x2 math.
#define TX       128                  // threads over f
#define TY       4                    // row groups
#define LTHREADS (TX * TY)            // 512
#define RG       4                    // rows per thread
#define ROWS     (TY * RG)            // 16 rows per block -> grid 128
#define FPT      4                    // f per thread per chunk (LDG.128)
#define NCHUNK   (F / (TX * FPT))     // 8
#define REDW     (LTHREADS / 32)      // 16 warps
#define SMEM_BYTES (C * F * 4)        // 160KB dynamic (pt)

__device__ float g_pt[C * F];         // pt[c*F + f] = exp(weight[c,f])
__device__ float g_ps[C * WSEG];     // segment partial sums of exp(weight[c,:])

// ---------- packed f32x2 helpers ----------
__device__ __forceinline__ unsigned long long pack2(float lo, float hi) {
    unsigned long long r;
    asm("mov.b64 %0, {%1, %2};" : "=l"(r) : "f"(lo), "f"(hi));
    return r;
}
__device__ __forceinline__ void unpack2(unsigned long long v, float& lo, float& hi) {
    asm("mov.b64 {%0, %1}, %2;" : "=f"(lo), "=f"(hi) : "l"(v));
}
__device__ __forceinline__ unsigned long long fma2(unsigned long long a,
                                                   unsigned long long b,
                                                   unsigned long long c) {
    unsigned long long d;
    asm("fma.rn.f32x2 %0, %1, %2, %3;" : "=l"(d) : "l"(a), "l"(b), "l"(c));
    return d;
}

// Kernel 1: exp(weight) + segment partial sums. 80 wide blocks, ~0.5us.
__global__ void wprep_kernel(const float* __restrict__ w) {
    const int c   = blockIdx.x >> 3;
    const int seg = blockIdx.x & 7;
    const int tid = threadIdx.x;
    const int f   = seg * WF + tid * 2;

    const float2 wv = *reinterpret_cast<const float2*>(w + (size_t)c * F + f);
    const float e0 = __expf(wv.x), e1 = __expf(wv.y);
    *reinterpret_cast<float2*>(g_pt + (size_t)c * F + f) = make_float2(e0, e1);

    float sum = e0 + e1;
    __shared__ float sred[NWARP];
    #pragma unroll
    for (int o = 16; o > 0; o >>= 1) sum += __shfl_xor_sync(0xffffffffu, sum, o);
    if ((tid & 31) == 0) sred[tid >> 5] = sum;
    __syncthreads();
    if (tid == 0) {
        float t = 0.f;
        #pragma unroll
        for (int i = 0; i < NWARP; i++) t += sred[i];
        g_ps[c * WSEG + seg] = t;
    }
}

// Kernel 2: out[b,c] = log( sum_f exp(x[b,f]) * pt[c,f] ) - log(sum_f pt[c,f])
// 512 threads (tx=128 over f, ty=4), RG=4 rows/thread; pt resident in smem;
// packed-f32x2 inner product; x prefetched one chunk ahead.
__global__ __launch_bounds__(LTHREADS, 1) void lse_kernel(const float* __restrict__ x,
                                                          float* __restrict__ out) {
    extern __shared__ float s_pt[];                     // C*F floats
    __shared__ float s_red[REDW][RG * C];

    const int tid = threadIdx.x;
    const int tx  = tid & (TX - 1);
    const int ty  = tid >> 7;
    const int b0  = blockIdx.x * ROWS + ty * RG;

    // Stage pt once: 10240 float4 over 512 threads -> 20 each, coalesced.
    {
        float4* s4 = reinterpret_cast<float4*>(s_pt);
        const float4* g4 = reinterpret_cast<const float4*>(g_pt);
        #pragma unroll
        for (int k = 0; k < (C * F / 4) / LTHREADS; k++)
            s4[tid + k * LTHREADS] = g4[tid + k * LTHREADS];
    }
    __syncthreads();   // the only sync before the reduction

    unsigned long long acc2[RG][C];
    #pragma unroll
    for (int r = 0; r < RG; r++)
        #pragma unroll
        for (int c = 0; c < C; c++) acc2[r][c] = 0ull;

    const float* xbase = x + (size_t)b0 * F;

    // Prefetch chunk 0.
    float4 xn[RG];
    #pragma unroll
    for (int r = 0; r < RG; r++)
        xn[r] = *reinterpret_cast<const float4*>(xbase + r * F + tx * FPT);

    #pragma unroll
    for (int ch = 0; ch < NCHUNK; ch++) {
        const int f = ch * (TX * FPT) + tx * FPT;

        // Consume xn into packed exponentials, freeing xn for the next prefetch.
        unsigned long long ea[RG], eb[RG];
        #pragma unroll
        for (int r = 0; r < RG; r++) {
            ea[r] = pack2(__expf(xn[r].x), __expf(xn[r].y));
            eb[r] = pack2(__expf(xn[r].z), __expf(xn[r].w));
        }

        // Prefetch next chunk's x while this chunk computes.
        if (ch + 1 < NCHUNK) {
            const int fn = (ch + 1) * (TX * FPT) + tx * FPT;
            #pragma unroll
            for (int r = 0; r < RG; r++)
                xn[r] = *reinterpret_cast<const float4*>(xbase + r * F + fn);
        }

        #pragma unroll
        for (int c = 0; c < C; c++) {
            const ulonglong2 pv =
                *reinterpret_cast<const ulonglong2*>(s_pt + c * F + f);
            #pragma unroll
            for (int r = 0; r < RG; r++) {
                acc2[r][c] = fma2(ea[r], pv.x, acc2[r][c]);
                acc2[r][c] = fma2(eb[r], pv.y, acc2[r][c]);
            }
        }
    }

    // Combine packed halves; reduce over tx (4 warps per ty group).
    #pragma unroll
    for (int r = 0; r < RG; r++)
        #pragma unroll
        for (int c = 0; c < C; c++) {
            float lo, hi;
            unpack2(acc2[r][c], lo, hi);
            float v = lo + hi;
            #pragma unroll
            for (int o = 16; o > 0; o >>= 1) v += __shfl_xor_sync(0xffffffffu, v, o);
            if ((tid & 31) == 0) s_red[tid >> 5][r * C + c] = v;
        }
    __syncthreads();

    if (tid < ROWS * C) {                                // 160 threads
        const int row = tid / C, c = tid % C;
        const int tyo = row / RG, r = row % RG;
        float s = 0.f;
        #pragma unroll
        for (int wi = 0; wi < TX / 32; wi++)
            s += s_red[tyo * (TX / 32) + wi][r * C + c];
        float z = 0.f;
        #pragma unroll
        for (int k = 0; k < WSEG; k++) z += g_ps[c * WSEG + k];
        out[(size_t)(blockIdx.x * ROWS + row) * C + c] = logf(s) - logf(z);
    }
}

extern "C" void kernel_launch(void* const* d_in, const int* in_sizes, int n_in,
                              void* d_out, int out_size) {
    const float* x = (const float*)d_in[0];   // (2048, 64, 64) fp32
    const float* w = (const float*)d_in[1];   // (10, 4096) fp32
    float* out = (float*)d_out;               // (2048, 10) fp32

    const int B = in_sizes[0] / F;            // 2048

    cudaFuncSetAttribute(lse_kernel, cudaFuncAttributeMaxDynamicSharedMemorySize,
                         SMEM_BYTES);

    wprep_kernel<<<C * WSEG, WPREP_T>>>(w);
    lse_kernel<<<B / ROWS, LTHREADS, SMEM_BYTES>>>(x, out);
}